// round 1
// baseline (speedup 1.0000x reference)
#include <cuda_runtime.h>
#include <cuda_bf16.h>

// out[b,s,d] = in[b,s,d] + pe(s,d)
//   pe(s,d) = sin(s * f(d)) if d even else cos(s * f(d)),  f(d) = 10000^(-2d/D)
//
// B=8, S=4096, D=1024, fp32. Memory-bound target: 268 MB traffic.
// Key amortizations:
//   - pe(s,d) computed ONCE per (s,d), reused across the 8-batch loop (registers)
//   - f(d) computed ONCE per thread (exp2f), reused across SS=8 s-rows
// Each thread owns one float4 (4 consecutive d) -> 128-bit coalesced ld/st.

constexpr int D  = 1024;
constexpr int S  = 4096;
constexpr int B  = 8;
constexpr int SS = 8;            // s-rows per block
constexpr int TPB = D / 4;       // 256 threads, one float4 of d each

__global__ __launch_bounds__(TPB, 8)
void pe_add_kernel(const float4* __restrict__ in, float4* __restrict__ out) {
    const int d4 = threadIdx.x;          // 0..255  (float4 column index)
    const int s0 = blockIdx.x * SS;      // first s-row of this block
    const int d  = d4 * 4;

    // f(d+j) = 10000^(-2(d+j)/1024) = exp2( -(d+j) * 2*log2(10000)/1024 )
    const float c = -2.0f * 13.287712379549449f / (float)D;  // log2(10000)
    const float f0 = exp2f(c * (float)(d + 0));
    const float f1 = exp2f(c * (float)(d + 1));
    const float f2 = exp2f(c * (float)(d + 2));
    const float f3 = exp2f(c * (float)(d + 3));

    #pragma unroll
    for (int si = 0; si < SS; ++si) {
        const int s = s0 + si;
        const float fs = (float)s;

        // d is a multiple of 4: lanes .x,.z are even dims (sin), .y,.w odd (cos)
        float4 pe;
        pe.x = __sinf(fs * f0);
        pe.y = __cosf(fs * f1);
        pe.z = __sinf(fs * f2);
        pe.w = __cosf(fs * f3);

        // batch loop: 8 independent 128-bit loads/stores, 16 MB apart (good MLP)
        const int row = s * TPB + d4;            // within one batch image
        #pragma unroll
        for (int b = 0; b < B; ++b) {
            const int idx = b * (S * TPB) + row; // max 8.4M float4 -> fits int
            float4 v = in[idx];
            v.x += pe.x;
            v.y += pe.y;
            v.z += pe.z;
            v.w += pe.w;
            out[idx] = v;
        }
    }
}

extern "C" void kernel_launch(void* const* d_in, const int* in_sizes, int n_in,
                              void* d_out, int out_size) {
    (void)in_sizes; (void)n_in; (void)out_size;
    const float4* in  = (const float4*)d_in[0];
    float4*       out = (float4*)d_out;
    pe_add_kernel<<<S / SS, TPB>>>(in, out);
}

// round 2
// speedup vs baseline: 1.4223x; 1.4223x over previous
#include <cuda_runtime.h>
#include <cuda_bf16.h>

// out[b,s,d] = in[b,s,d] + pe(s,d)
//   pe(s,d) = sin(s * f(d)) if d even else cos(s * f(d)),  f(d) = 10000^(-2d/D)
//
// B=8, S=4096, D=1024, fp32. 268 MB HBM traffic -> ~34us floor at 8TB/s.
// R2 changes vs R1:
//   - Batched loads: all 8 batch float4s loaded into v[8] BEFORE add/store
//     (forces MLP_p1 = 8; R1's regs=32 showed ptxas serialized ld->add->st).
//   - SS 8 -> 4: grid 512 -> 1024 blocks (occupancy 42% -> ~50%, reg-bound).
//   - Streaming cache hints (__ldcs/__stcs): zero-reuse 268MB stream, don't
//     thrash the 126MB L2.

constexpr int D  = 1024;
constexpr int S  = 4096;
constexpr int B  = 8;
constexpr int SS = 4;            // s-rows per block
constexpr int TPB = D / 4;       // 256 threads, one float4 of d each

__global__ __launch_bounds__(TPB, 4)
void pe_add_kernel(const float4* __restrict__ in, float4* __restrict__ out) {
    const int d4 = threadIdx.x;          // 0..255  (float4 column index)
    const int s0 = blockIdx.x * SS;      // first s-row of this block
    const int d  = d4 * 4;

    // f(d+j) = 10000^(-2(d+j)/1024) = exp2( -(d+j) * 2*log2(10000)/1024 )
    const float c = -2.0f * 13.287712379549449f / (float)D;  // log2(10000)
    const float f0 = exp2f(c * (float)(d + 0));
    const float f1 = exp2f(c * (float)(d + 1));
    const float f2 = exp2f(c * (float)(d + 2));
    const float f3 = exp2f(c * (float)(d + 3));

    #pragma unroll
    for (int si = 0; si < SS; ++si) {
        const int s = s0 + si;
        const float fs = (float)s;

        // d is a multiple of 4: lanes .x,.z are even dims (sin), .y,.w odd (cos)
        float4 pe;
        pe.x = __sinf(fs * f0);
        pe.y = __cosf(fs * f1);
        pe.z = __sinf(fs * f2);
        pe.w = __cosf(fs * f3);

        const int row = s * TPB + d4;            // within one batch image

        // Phase 1: issue ALL 8 loads back-to-back (MLP_p1 = 8)
        float4 v[B];
        #pragma unroll
        for (int b = 0; b < B; ++b) {
            v[b] = __ldcs(&in[b * (S * TPB) + row]);
        }

        // Phase 2: add + store
        #pragma unroll
        for (int b = 0; b < B; ++b) {
            float4 o;
            o.x = v[b].x + pe.x;
            o.y = v[b].y + pe.y;
            o.z = v[b].z + pe.z;
            o.w = v[b].w + pe.w;
            __stcs(&out[b * (S * TPB) + row], o);
        }
    }
}

extern "C" void kernel_launch(void* const* d_in, const int* in_sizes, int n_in,
                              void* d_out, int out_size) {
    (void)in_sizes; (void)n_in; (void)out_size;
    const float4* in  = (const float4*)d_in[0];
    float4*       out = (float4*)d_out;
    pe_add_kernel<<<S / SS, TPB>>>(in, out);
}